// round 12
// baseline (speedup 1.0000x reference)
#include <cuda_runtime.h>
#include <cuda_bf16.h>
#include <cstdint>

typedef unsigned long long ull;

#define VV 32000
#define EE 32
#define HH 128
#define BB 2
#define TT 512
#define RR (BB*TT)                       // 1024
#define GK 384                           // K of split GEMM: [hi|hi|lo] x [hi|lo|hi]
#define OFF_HID (RR*VV)                  // 32768000
#define OFF_W   (OFF_HID + BB*HH)        // 32768256

// ---------------- scratch (static device globals; no allocation) ----------------
__device__ float g_xp [RR*HH];
__device__ float g_rnn[RR*HH];
__device__ float g_q  [RR*HH];
__device__ float g_k  [RR*HH];
__device__ float g_ctx[RR*HH];
__device__ int   g_x64;
__device__ __align__(16) __nv_bfloat16 g_prjA[RR*GK];
__device__ __align__(16) __nv_bfloat16 g_wfcB[(size_t)VV*GK];

// ---------------- helpers ----------------
__device__ __forceinline__ void fma2(ull &d, ull a, ull b) {
    asm("fma.rn.f32x2 %0, %1, %2, %0;" : "+l"(d) : "l"(a), "l"(b));
}
__device__ __forceinline__ void add2(ull &d, ull a) {
    asm("add.rn.f32x2 %0, %0, %1;" : "+l"(d) : "l"(a));
}
__device__ __forceinline__ float ull_lo(ull u){ return __uint_as_float((unsigned)(u & 0xffffffffull)); }
__device__ __forceinline__ float ull_hi(ull u){ return __uint_as_float((unsigned)(u >> 32)); }

__device__ __forceinline__ float tanh_fast(float x) {
    float e = __expf(2.0f * x);
    return 1.0f - __fdividef(2.0f, e + 1.0f);
}
__device__ __forceinline__ float tanh_approx(float x) {
    float y;
    asm("tanh.approx.f32 %0, %1;" : "=f"(y) : "f"(x));
    return y;
}
__device__ __forceinline__ void bf16_split(float f, __nv_bfloat16 &hi, __nv_bfloat16 &lo) {
    hi = __float2bfloat16(f);
    lo = __float2bfloat16(f - __bfloat162float(hi));
}
__device__ __forceinline__ uint32_t smem_to_u32(const void* p) {
    uint32_t a;
    asm("{ .reg .u64 t; cvta.to.shared.u64 t, %1; cvt.u32.u64 %0, t; }" : "=r"(a) : "l"(p));
    return a;
}

// ---------------- K0: detect int64 vs int32 ids ----------------
__global__ void detect_kernel(const int* __restrict__ x32) {
    __shared__ int bad;
    if (threadIdx.x == 0) bad = 0;
    __syncthreads();
    for (int i = threadIdx.x; i < 512; i += blockDim.x)
        if (x32[2*i + 1] != 0) atomicExch(&bad, 1);
    __syncthreads();
    if (threadIdx.x == 0) g_x64 = bad ? 0 : 1;
}

// ---------------- K1: embedding + input projection ----------------
__global__ void embed_kernel(const int* __restrict__ x32,
                             const float* __restrict__ et,
                             const float* __restrict__ W_ih,
                             const float* __restrict__ b_ih,
                             const float* __restrict__ b_hh) {
    __shared__ float e_sh[EE];
    __shared__ float Wsh[HH * 33];
    int r = blockIdx.x;
    int h = threadIdx.x;
    for (int j = h; j < HH * EE; j += HH) {
        int hh = j >> 5, ee = j & 31;
        Wsh[hh * 33 + ee] = W_ih[j];
    }
    int id = g_x64 ? x32[2 * r] : x32[r];
    if (h < EE) e_sh[h] = et[id * EE + h];
    __syncthreads();
    float acc = b_ih[h] + b_hh[h];
#pragma unroll
    for (int e = 0; e < EE; e++) acc += Wsh[h * 33 + e] * e_sh[e];
    g_xp[r * HH + h] = acc;
}

// ---------------- K2: sequential RNN scan (256 thr, 2-way K split, depth-2 xp pipeline) ----------------
__global__ void __launch_bounds__(256, 1) rnn_kernel(const float* __restrict__ hidden,
                                                     const float* __restrict__ W_hh,
                                                     float* __restrict__ out_hid) {
    __shared__ __align__(16) float h_sh[2][HH];
    int b = blockIdx.x;
    int tid = threadIdx.x;
    int h = tid >> 1, part = tid & 1;

    // thread (h, part) holds W_hh[h][part*64 .. +64) as 32 packed f32x2 regs
    ull w2[32];
    {
        const ulonglong2* wp = (const ulonglong2*)(W_hh + h * HH + part * 64);
#pragma unroll
        for (int i = 0; i < 16; i++) { ulonglong2 v = wp[i]; w2[2*i] = v.x; w2[2*i+1] = v.y; }
    }
    if (tid < HH) h_sh[0][tid] = hidden[b * HH + tid];
    __syncthreads();

    const float* xpb = g_xp + b * TT * HH;
    float* rnnb = g_rnn + b * TT * HH;

    // xp register pipeline, depth 2 (only part==0 consumes xp)
    float x0 = 0.f, x1 = 0.f;
    if (part == 0) { x0 = xpb[h]; x1 = xpb[HH + h]; }

#pragma unroll 2
    for (int t = 0; t < TT; t++) {
        int cur = t & 1;
        float xnew = 0.f;
        if (part == 0 && t + 2 < TT) xnew = xpb[(t + 2) * HH + h];   // prefetch t+2

        const ulonglong2* hp = (const ulonglong2*)&h_sh[cur][part * 64];
        ull a0 = 0ull, a1 = 0ull, a2 = 0ull, a3 = 0ull;
#pragma unroll
        for (int i = 0; i < 8; i++) {
            ulonglong2 u = hp[2*i];
            ulonglong2 v = hp[2*i+1];
            fma2(a0, w2[4*i+0], u.x);
            fma2(a1, w2[4*i+1], u.y);
            fma2(a2, w2[4*i+2], v.x);
            fma2(a3, w2[4*i+3], v.y);
        }
        add2(a0, a1);
        add2(a2, a3);
        add2(a0, a2);
        float s = ull_lo(a0) + ull_hi(a0);
        s += __shfl_xor_sync(0xffffffffu, s, 1);   // combine part 0/1 (adjacent lanes)
        if (part == 0) {
            float hn = tanh_fast(x0 + s);
            h_sh[cur ^ 1][h] = hn;
            rnnb[t * HH + h] = hn;
        }
        x0 = x1; x1 = xnew;
        __syncthreads();
    }
    if (part == 0) out_hid[b * HH + h] = h_sh[0][h];
}

// ---------------- K3: q = rnn@W1^T, k = rnn@W2^T ----------------
__global__ __launch_bounds__(256, 2) void qk_kernel(const float* __restrict__ W1,
                                                    const float* __restrict__ W2) {
    extern __shared__ float qsm[];
    float* Wt  = qsm;              // [k=128][h=128] pitch 132
    float* rsh = qsm + 128 * 132;  // [r=32][k=128] pitch 132
    int wsel = blockIdx.x >> 5, tc = blockIdx.x & 31;
    const float* W = wsel ? W2 : W1;
    int tid = threadIdx.x;

#pragma unroll
    for (int it = 0; it < 16; it++) {
        int j = it * 256 + tid;
        int h = j >> 5, k4 = j & 31;
        float4 f = *(const float4*)&W[h * HH + k4 * 4];
        Wt[(k4 * 4 + 0) * 132 + h] = f.x;
        Wt[(k4 * 4 + 1) * 132 + h] = f.y;
        Wt[(k4 * 4 + 2) * 132 + h] = f.z;
        Wt[(k4 * 4 + 3) * 132 + h] = f.w;
    }
#pragma unroll
    for (int it = 0; it < 4; it++) {
        int j = it * 256 + tid;
        int r = j >> 5, k4 = j & 31;
        *(float4*)&rsh[r * 132 + k4 * 4] = *(const float4*)&g_rnn[(tc * 32 + r) * HH + k4 * 4];
    }
    __syncthreads();

    int h = tid & 127, rg = tid >> 7;
    float acc[16];
#pragma unroll
    for (int i = 0; i < 16; i++) acc[i] = 0.f;

    for (int k = 0; k < 128; k += 4) {
        float w0 = Wt[(k + 0) * 132 + h];
        float w1 = Wt[(k + 1) * 132 + h];
        float w2v = Wt[(k + 2) * 132 + h];
        float w3 = Wt[(k + 3) * 132 + h];
#pragma unroll
        for (int rr = 0; rr < 16; rr++) {
            float4 rv = *(const float4*)&rsh[(rg * 16 + rr) * 132 + k];
            acc[rr] += w0 * rv.x + w1 * rv.y + w2v * rv.z + w3 * rv.w;
        }
    }
    float* dst = wsel ? g_k : g_q;
#pragma unroll
    for (int rr = 0; rr < 16; rr++)
        dst[(tc * 32 + rg * 16 + rr) * HH + h] = acc[rr];
}

// ---------------- K4: additive attention (q/v preloaded to registers) ----------------
__global__ void attn_kernel(const float* __restrict__ v, float* __restrict__ wout) {
    __shared__ float q_sh[HH], v_sh[HH];
    __shared__ float ksh[64 * 132];
    __shared__ float sc[TT];
    __shared__ float red[8];
    __shared__ float redval;
    __shared__ float ctxp[HH];

    int bx = blockIdx.x;
    int b = bx >> 9, t = bx & 511;
    int tid = threadIdx.x;
    int r = b * TT + t;
    int n = t + 1;

    if (tid < HH) { q_sh[tid] = g_q[r * HH + tid]; v_sh[tid] = v[tid]; }
    __syncthreads();

    int sl = tid >> 2, qq = tid & 3;

    // hoist loop-invariant q/v values into registers (64 regs/thread)
    float qv[32], vv[32];
#pragma unroll
    for (int i = 0; i < 32; i++) {
        qv[i] = q_sh[qq + 4 * i];
        vv[i] = v_sh[qq + 4 * i];
    }

    for (int s0 = 0; s0 < n; s0 += 64) {
        int cnt = min(64, n - s0);
        __syncthreads();
        for (int j = tid; j < cnt * HH; j += 256) {
            int ss = j >> 7, hh = j & 127;
            ksh[ss * 132 + hh] = g_k[(b * TT + s0 + ss) * HH + hh];
        }
        __syncthreads();
        float acc = 0.f;
        if (sl < cnt) {
            const float* kr = &ksh[sl * 132 + qq];
#pragma unroll 8
            for (int i = 0; i < 32; i++)
                acc += vv[i] * tanh_approx(qv[i] + kr[4 * i]);
        }
        acc += __shfl_xor_sync(0xffffffffu, acc, 1);
        acc += __shfl_xor_sync(0xffffffffu, acc, 2);
        if (qq == 0 && sl < cnt) sc[s0 + sl] = acc;
    }
    __syncthreads();

    float m = -1e30f;
    for (int s = tid; s < n; s += 256) m = fmaxf(m, sc[s]);
#pragma unroll
    for (int o = 16; o; o >>= 1) m = fmaxf(m, __shfl_xor_sync(0xffffffffu, m, o));
    if ((tid & 31) == 0) red[tid >> 5] = m;
    __syncthreads();
    if (tid == 0) {
        float mm = red[0];
#pragma unroll
        for (int i = 1; i < 8; i++) mm = fmaxf(mm, red[i]);
        redval = mm;
    }
    __syncthreads();
    m = redval;

    float ssum = 0.f;
    for (int s = tid; s < n; s += 256) {
        float e = __expf(sc[s] - m);
        sc[s] = e;
        ssum += e;
    }
#pragma unroll
    for (int o = 16; o; o >>= 1) ssum += __shfl_xor_sync(0xffffffffu, ssum, o);
    __syncthreads();
    if ((tid & 31) == 0) red[tid >> 5] = ssum;
    __syncthreads();
    if (tid == 0) {
        float s2 = 0.f;
#pragma unroll
        for (int i = 0; i < 8; i++) s2 += red[i];
        redval = s2;
    }
    __syncthreads();
    float inv = __fdividef(1.0f, redval);

    for (int s = tid; s < TT; s += 256) {
        float w = (s < n) ? sc[s] * inv : 0.f;
        if (s < n) sc[s] = w;
        wout[(size_t)r * TT + s] = w;
    }
    __syncthreads();

    int h = tid & 127, g = tid >> 7;
    float acc = 0.f;
    for (int s = g; s < n; s += 2)
        acc += sc[s] * g_rnn[(b * TT + s) * HH + h];
    if (g == 1) ctxp[h] = acc;
    __syncthreads();
    if (g == 0) g_ctx[r * HH + h] = acc + ctxp[h];
}

// ---------------- K5: out = relu([rnn|ctx] @ Wp^T + bp) -> A' = [hi|hi|lo] bf16 ----------------
__global__ void proj_kernel(const float* __restrict__ Wp, const float* __restrict__ bp) {
    __shared__ float comb[16 * 256];
    __shared__ float Wsh[HH * 33];
    int bx = blockIdx.x;
    int b = bx >> 5, tc = bx & 31;
    int tid = threadIdx.x;
    int h = tid & 127, g = tid >> 7;
    int rbase = b * TT + tc * 16;

    for (int j = tid; j < 16 * HH; j += 256) {
        int tt = j >> 7, k = j & 127;
        comb[tt * 256 + k]        = g_rnn[(rbase + tt) * HH + k];
        comb[tt * 256 + 128 + k]  = g_ctx[(rbase + tt) * HH + k];
    }
    float acc[8];
#pragma unroll
    for (int i = 0; i < 8; i++) acc[i] = 0.f;

    for (int kc = 0; kc < 256; kc += 32) {
        __syncthreads();
        for (int j = tid; j < HH * 32; j += 256) {
            int hh = j >> 5, kk = j & 31;
            Wsh[hh * 33 + kk] = Wp[hh * 256 + kc + kk];
        }
        __syncthreads();
#pragma unroll
        for (int kk = 0; kk < 32; kk++) {
            float w = Wsh[h * 33 + kk];
#pragma unroll
            for (int tt = 0; tt < 8; tt++)
                acc[tt] += w * comb[(g * 8 + tt) * 256 + kc + kk];
        }
    }
    float bb = bp[h];
#pragma unroll
    for (int tt = 0; tt < 8; tt++) {
        float o = fmaxf(acc[tt] + bb, 0.f);
        size_t row = rbase + g * 8 + tt;
        __nv_bfloat16 hi, lo;
        bf16_split(o, hi, lo);
        g_prjA[row * GK + h]       = hi;
        g_prjA[row * GK + 128 + h] = hi;
        g_prjA[row * GK + 256 + h] = lo;
    }
}

// ---------------- K5b: Wfc -> B' = [hi|lo|hi] bf16 ----------------
__global__ void wfc_prep_kernel(const float* __restrict__ Wfc) {
    int j = blockIdx.x * 256 + threadIdx.x;   // over VV*HH/4 float4s
    float4 f = *(const float4*)&Wfc[(size_t)j * 4];
    int row = j >> 5;
    int col = (j & 31) * 4;
    __nv_bfloat16 h[4], l[4];
    bf16_split(f.x, h[0], l[0]);
    bf16_split(f.y, h[1], l[1]);
    bf16_split(f.z, h[2], l[2]);
    bf16_split(f.w, h[3], l[3]);
    size_t base = (size_t)row * GK;
    __nv_bfloat162* p0 = (__nv_bfloat162*)&g_wfcB[base + col];
    __nv_bfloat162* p1 = (__nv_bfloat162*)&g_wfcB[base + 128 + col];
    __nv_bfloat162* p2 = (__nv_bfloat162*)&g_wfcB[base + 256 + col];
    p0[0] = __nv_bfloat162(h[0], h[1]); p0[1] = __nv_bfloat162(h[2], h[3]);
    p1[0] = __nv_bfloat162(l[0], l[1]); p1[1] = __nv_bfloat162(l[2], l[3]);
    p2[0] = __nv_bfloat162(h[0], h[1]); p2[1] = __nv_bfloat162(h[2], h[3]);
}

// ---------------- K6: logits = A'(1024xGK) @ B'(32000xGK)^T + bfc, via mma.sync bf16 ----------------
#define NCHUNK (GK/64)   // 6
__global__ __launch_bounds__(256, 2) void logits_mma_kernel(const float* __restrict__ bfc,
                                                            float* __restrict__ out) {
    extern __shared__ char sm[];
    uint32_t smb = smem_to_u32(sm);
    float* biassh = (float*)(sm + 65536);
    int vbase = blockIdx.x * 128;
    int rbase = blockIdx.y * 128;
    int tid = threadIdx.x;
    int wid = tid >> 5, lane = tid & 31;

    if (tid < 128) biassh[tid] = bfc[vbase + tid];

    auto stage = [&](int s, int c) {
        const char* srcA = (const char*)(g_prjA + (size_t)rbase * GK + c * 64);
        const char* srcB = (const char*)(g_wfcB + (size_t)vbase * GK + c * 64);
#pragma unroll
        for (int it = 0; it < 4; it++) {
            int j = it * 256 + tid;
            int r = j >> 3, cc = j & 7;
            uint32_t swoff = (uint32_t)(r * 128 + ((cc ^ (r & 7)) << 4));
            uint32_t dA = smb + s * 32768 + swoff;
            uint32_t dB = smb + s * 32768 + 16384 + swoff;
            const char* sA = srcA + (size_t)r * (GK * 2) + cc * 16;
            const char* sB = srcB + (size_t)r * (GK * 2) + cc * 16;
            asm volatile("cp.async.cg.shared.global [%0], [%1], 16;" :: "r"(dA), "l"(sA));
            asm volatile("cp.async.cg.shared.global [%0], [%1], 16;" :: "r"(dB), "l"(sB));
        }
        asm volatile("cp.async.commit_group;");
    };

    int warp_m = wid >> 2, warp_n = wid & 3;

    float acc[4][4][4];
#pragma unroll
    for (int i = 0; i < 4; i++)
#pragma unroll
        for (int j = 0; j < 4; j++)
#pragma unroll
            for (int p = 0; p < 4; p++) acc[i][j][p] = 0.f;

    stage(0, 0);
    stage(1, 1);

    int arowc = (lane & 7) + ((lane >> 3) & 1) * 8;
    int chnksel = lane >> 4;

    for (int c = 0; c < NCHUNK; c++) {
        if (c == NCHUNK - 1) { asm volatile("cp.async.wait_group 0;" ::: "memory"); }
        else                 { asm volatile("cp.async.wait_group 1;" ::: "memory"); }
        __syncthreads();
        uint32_t Ab = smb + (c & 1) * 32768;
        uint32_t Bb = Ab + 16384;
#pragma unroll
        for (int kk = 0; kk < 4; kk++) {
            uint32_t a[4][4], bfr[2][4];
            int chnk = kk * 2 + chnksel;
#pragma unroll
            for (int mt = 0; mt < 4; mt++) {
                int row = warp_m * 64 + mt * 16 + arowc;
                uint32_t addr = Ab + row * 128 + ((chnk ^ (row & 7)) << 4);
                asm volatile("ldmatrix.sync.aligned.m8n8.x4.shared.b16 {%0,%1,%2,%3}, [%4];"
                    : "=r"(a[mt][0]), "=r"(a[mt][1]), "=r"(a[mt][2]), "=r"(a[mt][3]) : "r"(addr));
            }
#pragma unroll
            for (int bp = 0; bp < 2; bp++) {
                int row = warp_n * 32 + bp * 16 + arowc;
                uint32_t addr = Bb + row * 128 + ((chnk ^ (row & 7)) << 4);
                asm volatile("ldmatrix.sync.aligned.m8n8.x4.shared.b16 {%0,%1,%2,%3}, [%4];"
                    : "=r"(bfr[bp][0]), "=r"(bfr[bp][1]), "=r"(bfr[bp][2]), "=r"(bfr[bp][3]) : "r"(addr));
            }
#pragma unroll
            for (int mt = 0; mt < 4; mt++)
#pragma unroll
                for (int nt = 0; nt < 4; nt++) {
                    uint32_t b0 = bfr[nt >> 1][(nt & 1) ? 1 : 0];
                    uint32_t b1 = bfr[nt >> 1][(nt & 1) ? 3 : 2];
                    asm volatile("mma.sync.aligned.m16n8k16.row.col.f32.bf16.bf16.f32 "
                        "{%0,%1,%2,%3}, {%4,%5,%6,%7}, {%8,%9}, {%0,%1,%2,%3};"
                        : "+f"(acc[mt][nt][0]), "+f"(acc[mt][nt][1]),
                          "+f"(acc[mt][nt][2]), "+f"(acc[mt][nt][3])
                        : "r"(a[mt][0]), "r"(a[mt][1]), "r"(a[mt][2]), "r"(a[mt][3]),
                          "r"(b0), "r"(b1));
                }
        }
        __syncthreads();
        if (c + 2 < NCHUNK) stage(c & 1, c + 2);
    }

    int rquad = lane >> 2, cpair = (lane & 3) * 2;
#pragma unroll
    for (int mt = 0; mt < 4; mt++) {
#pragma unroll
        for (int nt = 0; nt < 4; nt++) {
            int col = warp_n * 32 + nt * 8 + cpair;
            float bx = biassh[col], by = biassh[col + 1];
            size_t row0 = (size_t)rbase + warp_m * 64 + mt * 16 + rquad;
            float2 v0 = { acc[mt][nt][0] + bx, acc[mt][nt][1] + by };
            float2 v1 = { acc[mt][nt][2] + bx, acc[mt][nt][3] + by };
            *(float2*)&out[row0 * VV + vbase + col]       = v0;
            *(float2*)&out[(row0 + 8) * VV + vbase + col] = v1;
        }
    }
}

// ---------------- launch ----------------
extern "C" void kernel_launch(void* const* d_in, const int* in_sizes, int n_in,
                              void* d_out, int out_size) {
    const int*   x32    = (const int*)  d_in[0];
    const float* hidden = (const float*)d_in[1];
    const float* et     = (const float*)d_in[2];
    const float* W_ih   = (const float*)d_in[3];
    const float* W_hh   = (const float*)d_in[4];
    const float* b_ih   = (const float*)d_in[5];
    const float* b_hh   = (const float*)d_in[6];
    const float* W1     = (const float*)d_in[7];
    const float* W2     = (const float*)d_in[8];
    const float* v      = (const float*)d_in[9];
    const float* Wp     = (const float*)d_in[10];
    const float* bp     = (const float*)d_in[11];
    const float* Wfc    = (const float*)d_in[12];
    const float* bfc    = (const float*)d_in[13];
    float* out = (float*)d_out;

    cudaFuncSetAttribute(qk_kernel,         cudaFuncAttributeMaxDynamicSharedMemorySize, 84480);
    cudaFuncSetAttribute(logits_mma_kernel, cudaFuncAttributeMaxDynamicSharedMemorySize, 66048);

    detect_kernel<<<1, 256>>>(x32);
    embed_kernel<<<RR, HH>>>(x32, et, W_ih, b_ih, b_hh);
    wfc_prep_kernel<<<VV * HH / 1024, 256>>>(Wfc);
    rnn_kernel<<<BB, 256>>>(hidden, W_hh, out + OFF_HID);
    qk_kernel<<<64, 256, 84480>>>(W1, W2);
    attn_kernel<<<RR, 256>>>(v, out + OFF_W);
    proj_kernel<<<64, 256>>>(Wp, bp);
    logits_mma_kernel<<<dim3(VV / 128, RR / 128), 256, 66048>>>(bfc, out);
}

// round 13
// speedup vs baseline: 1.1589x; 1.1589x over previous
#include <cuda_runtime.h>
#include <cuda_bf16.h>
#include <cstdint>

typedef unsigned long long ull;

#define VV 32000
#define EE 32
#define HH 128
#define BB 2
#define TT 512
#define RR (BB*TT)                       // 1024
#define GK 384                           // K of split GEMM: [hi|hi|lo] x [hi|lo|hi]
#define OFF_HID (RR*VV)                  // 32768000
#define OFF_W   (OFF_HID + BB*HH)        // 32768256

// ---------------- scratch (static device globals; no allocation) ----------------
__device__ float g_xp [RR*HH];
__device__ float g_rnn[RR*HH];
__device__ float g_q  [RR*HH];
__device__ float g_k  [RR*HH];
__device__ float g_ctx[RR*HH];
__device__ int   g_x64;
__device__ __align__(16) __nv_bfloat16 g_prjA[RR*GK];
__device__ __align__(16) __nv_bfloat16 g_wfcB[(size_t)VV*GK];

// ---------------- helpers ----------------
__device__ __forceinline__ void fma2(ull &d, ull a, ull b) {
    asm("fma.rn.f32x2 %0, %1, %2, %0;" : "+l"(d) : "l"(a), "l"(b));
}
__device__ __forceinline__ void add2(ull &d, ull a) {
    asm("add.rn.f32x2 %0, %0, %1;" : "+l"(d) : "l"(a));
}
__device__ __forceinline__ float ull_lo(ull u){ return __uint_as_float((unsigned)(u & 0xffffffffull)); }
__device__ __forceinline__ float ull_hi(ull u){ return __uint_as_float((unsigned)(u >> 32)); }

__device__ __forceinline__ float tanh_fast(float x) {
    float e = __expf(2.0f * x);
    return 1.0f - __fdividef(2.0f, e + 1.0f);
}
__device__ __forceinline__ float tanh_approx(float x) {
    float y;
    asm("tanh.approx.f32 %0, %1;" : "=f"(y) : "f"(x));
    return y;
}
__device__ __forceinline__ void bf16_split(float f, __nv_bfloat16 &hi, __nv_bfloat16 &lo) {
    hi = __float2bfloat16(f);
    lo = __float2bfloat16(f - __bfloat162float(hi));
}
__device__ __forceinline__ uint32_t smem_to_u32(const void* p) {
    uint32_t a;
    asm("{ .reg .u64 t; cvta.to.shared.u64 t, %1; cvt.u32.u64 %0, t; }" : "=r"(a) : "l"(p));
    return a;
}

// ---------------- K0: detect int64 vs int32 ids ----------------
__global__ void detect_kernel(const int* __restrict__ x32) {
    __shared__ int bad;
    if (threadIdx.x == 0) bad = 0;
    __syncthreads();
    for (int i = threadIdx.x; i < 512; i += blockDim.x)
        if (x32[2*i + 1] != 0) atomicExch(&bad, 1);
    __syncthreads();
    if (threadIdx.x == 0) g_x64 = bad ? 0 : 1;
}

// ---------------- K1: embedding + input projection ----------------
__global__ void embed_kernel(const int* __restrict__ x32,
                             const float* __restrict__ et,
                             const float* __restrict__ W_ih,
                             const float* __restrict__ b_ih,
                             const float* __restrict__ b_hh) {
    __shared__ float e_sh[EE];
    __shared__ float Wsh[HH * 33];
    int r = blockIdx.x;
    int h = threadIdx.x;
    for (int j = h; j < HH * EE; j += HH) {
        int hh = j >> 5, ee = j & 31;
        Wsh[hh * 33 + ee] = W_ih[j];
    }
    int id = g_x64 ? x32[2 * r] : x32[r];
    if (h < EE) e_sh[h] = et[id * EE + h];
    __syncthreads();
    float acc = b_ih[h] + b_hh[h];
#pragma unroll
    for (int e = 0; e < EE; e++) acc += Wsh[h * 33 + e] * e_sh[e];
    g_xp[r * HH + h] = acc;
}

// ---------------- K2: sequential RNN scan (128 thr, full row per thread, no shuffle) ----------------
__global__ void __launch_bounds__(128, 1) rnn_kernel(const float* __restrict__ hidden,
                                                     const float* __restrict__ W_hh,
                                                     float* __restrict__ out_hid) {
    __shared__ __align__(16) float h_sh[2][HH];
    int b = blockIdx.x;
    int h = threadIdx.x;   // 0..127, one output row per thread

    // thread h holds the FULL W_hh row: 128 weights = 64 packed f32x2 regs
    ull w2[64];
    {
        const ulonglong2* wp = (const ulonglong2*)(W_hh + h * HH);
#pragma unroll
        for (int i = 0; i < 32; i++) { ulonglong2 v = wp[i]; w2[2*i] = v.x; w2[2*i+1] = v.y; }
    }
    h_sh[0][h] = hidden[b * HH + h];
    __syncthreads();

    const float* xpb = g_xp + b * TT * HH;
    float* rnnb = g_rnn + b * TT * HH;

    // xp register pipeline, depth 2
    float x0 = xpb[h];
    float x1 = xpb[HH + h];

#pragma unroll 2
    for (int t = 0; t < TT; t++) {
        int cur = t & 1;
        float xnew = (t + 2 < TT) ? xpb[(t + 2) * HH + h] : 0.f;   // prefetch t+2

        const ulonglong2* hp = (const ulonglong2*)&h_sh[cur][0];
        ull a[8];
#pragma unroll
        for (int c = 0; c < 8; c++) a[c] = 0ull;
        // 64 fma2 spread round-robin over 8 independent chains (8 deep each)
#pragma unroll
        for (int i = 0; i < 32; i++) {
            ulonglong2 u = hp[i];
            fma2(a[(2*i)     & 7], w2[2*i],     u.x);
            fma2(a[(2*i + 1) & 7], w2[2*i + 1], u.y);
        }
        add2(a[0], a[4]);
        add2(a[1], a[5]);
        add2(a[2], a[6]);
        add2(a[3], a[7]);
        add2(a[0], a[2]);
        add2(a[1], a[3]);
        add2(a[0], a[1]);
        float s = ull_lo(a[0]) + ull_hi(a[0]);

        float hn = tanh_fast(x0 + s);
        h_sh[cur ^ 1][h] = hn;
        rnnb[t * HH + h] = hn;

        x0 = x1; x1 = xnew;
        __syncthreads();
    }
    out_hid[b * HH + h] = h_sh[0][h];
}

// ---------------- K3: q = rnn@W1^T, k = rnn@W2^T ----------------
__global__ __launch_bounds__(256, 2) void qk_kernel(const float* __restrict__ W1,
                                                    const float* __restrict__ W2) {
    extern __shared__ float qsm[];
    float* Wt  = qsm;              // [k=128][h=128] pitch 132
    float* rsh = qsm + 128 * 132;  // [r=32][k=128] pitch 132
    int wsel = blockIdx.x >> 5, tc = blockIdx.x & 31;
    const float* W = wsel ? W2 : W1;
    int tid = threadIdx.x;

#pragma unroll
    for (int it = 0; it < 16; it++) {
        int j = it * 256 + tid;
        int h = j >> 5, k4 = j & 31;
        float4 f = *(const float4*)&W[h * HH + k4 * 4];
        Wt[(k4 * 4 + 0) * 132 + h] = f.x;
        Wt[(k4 * 4 + 1) * 132 + h] = f.y;
        Wt[(k4 * 4 + 2) * 132 + h] = f.z;
        Wt[(k4 * 4 + 3) * 132 + h] = f.w;
    }
#pragma unroll
    for (int it = 0; it < 4; it++) {
        int j = it * 256 + tid;
        int r = j >> 5, k4 = j & 31;
        *(float4*)&rsh[r * 132 + k4 * 4] = *(const float4*)&g_rnn[(tc * 32 + r) * HH + k4 * 4];
    }
    __syncthreads();

    int h = tid & 127, rg = tid >> 7;
    float acc[16];
#pragma unroll
    for (int i = 0; i < 16; i++) acc[i] = 0.f;

    for (int k = 0; k < 128; k += 4) {
        float w0 = Wt[(k + 0) * 132 + h];
        float w1 = Wt[(k + 1) * 132 + h];
        float w2v = Wt[(k + 2) * 132 + h];
        float w3 = Wt[(k + 3) * 132 + h];
#pragma unroll
        for (int rr = 0; rr < 16; rr++) {
            float4 rv = *(const float4*)&rsh[(rg * 16 + rr) * 132 + k];
            acc[rr] += w0 * rv.x + w1 * rv.y + w2v * rv.z + w3 * rv.w;
        }
    }
    float* dst = wsel ? g_k : g_q;
#pragma unroll
    for (int rr = 0; rr < 16; rr++)
        dst[(tc * 32 + rg * 16 + rr) * HH + h] = acc[rr];
}

// ---------------- K4: additive attention (q/v preloaded to registers) ----------------
__global__ void attn_kernel(const float* __restrict__ v, float* __restrict__ wout) {
    __shared__ float q_sh[HH], v_sh[HH];
    __shared__ float ksh[64 * 132];
    __shared__ float sc[TT];
    __shared__ float red[8];
    __shared__ float redval;
    __shared__ float ctxp[HH];

    int bx = blockIdx.x;
    int b = bx >> 9, t = bx & 511;
    int tid = threadIdx.x;
    int r = b * TT + t;
    int n = t + 1;

    if (tid < HH) { q_sh[tid] = g_q[r * HH + tid]; v_sh[tid] = v[tid]; }
    __syncthreads();

    int sl = tid >> 2, qq = tid & 3;

    // hoist loop-invariant q/v values into registers (64 regs/thread)
    float qv[32], vv[32];
#pragma unroll
    for (int i = 0; i < 32; i++) {
        qv[i] = q_sh[qq + 4 * i];
        vv[i] = v_sh[qq + 4 * i];
    }

    for (int s0 = 0; s0 < n; s0 += 64) {
        int cnt = min(64, n - s0);
        __syncthreads();
        for (int j = tid; j < cnt * HH; j += 256) {
            int ss = j >> 7, hh = j & 127;
            ksh[ss * 132 + hh] = g_k[(b * TT + s0 + ss) * HH + hh];
        }
        __syncthreads();
        float acc = 0.f;
        if (sl < cnt) {
            const float* kr = &ksh[sl * 132 + qq];
#pragma unroll 8
            for (int i = 0; i < 32; i++)
                acc += vv[i] * tanh_approx(qv[i] + kr[4 * i]);
        }
        acc += __shfl_xor_sync(0xffffffffu, acc, 1);
        acc += __shfl_xor_sync(0xffffffffu, acc, 2);
        if (qq == 0 && sl < cnt) sc[s0 + sl] = acc;
    }
    __syncthreads();

    float m = -1e30f;
    for (int s = tid; s < n; s += 256) m = fmaxf(m, sc[s]);
#pragma unroll
    for (int o = 16; o; o >>= 1) m = fmaxf(m, __shfl_xor_sync(0xffffffffu, m, o));
    if ((tid & 31) == 0) red[tid >> 5] = m;
    __syncthreads();
    if (tid == 0) {
        float mm = red[0];
#pragma unroll
        for (int i = 1; i < 8; i++) mm = fmaxf(mm, red[i]);
        redval = mm;
    }
    __syncthreads();
    m = redval;

    float ssum = 0.f;
    for (int s = tid; s < n; s += 256) {
        float e = __expf(sc[s] - m);
        sc[s] = e;
        ssum += e;
    }
#pragma unroll
    for (int o = 16; o; o >>= 1) ssum += __shfl_xor_sync(0xffffffffu, ssum, o);
    __syncthreads();
    if ((tid & 31) == 0) red[tid >> 5] = ssum;
    __syncthreads();
    if (tid == 0) {
        float s2 = 0.f;
#pragma unroll
        for (int i = 0; i < 8; i++) s2 += red[i];
        redval = s2;
    }
    __syncthreads();
    float inv = __fdividef(1.0f, redval);

    for (int s = tid; s < TT; s += 256) {
        float w = (s < n) ? sc[s] * inv : 0.f;
        if (s < n) sc[s] = w;
        wout[(size_t)r * TT + s] = w;
    }
    __syncthreads();

    int h = tid & 127, g = tid >> 7;
    float acc = 0.f;
    for (int s = g; s < n; s += 2)
        acc += sc[s] * g_rnn[(b * TT + s) * HH + h];
    if (g == 1) ctxp[h] = acc;
    __syncthreads();
    if (g == 0) g_ctx[r * HH + h] = acc + ctxp[h];
}

// ---------------- K5: out = relu([rnn|ctx] @ Wp^T + bp) -> A' = [hi|hi|lo] bf16 ----------------
__global__ void proj_kernel(const float* __restrict__ Wp, const float* __restrict__ bp) {
    __shared__ float comb[16 * 256];
    __shared__ float Wsh[HH * 33];
    int bx = blockIdx.x;
    int b = bx >> 5, tc = bx & 31;
    int tid = threadIdx.x;
    int h = tid & 127, g = tid >> 7;
    int rbase = b * TT + tc * 16;

    for (int j = tid; j < 16 * HH; j += 256) {
        int tt = j >> 7, k = j & 127;
        comb[tt * 256 + k]        = g_rnn[(rbase + tt) * HH + k];
        comb[tt * 256 + 128 + k]  = g_ctx[(rbase + tt) * HH + k];
    }
    float acc[8];
#pragma unroll
    for (int i = 0; i < 8; i++) acc[i] = 0.f;

    for (int kc = 0; kc < 256; kc += 32) {
        __syncthreads();
        for (int j = tid; j < HH * 32; j += 256) {
            int hh = j >> 5, kk = j & 31;
            Wsh[hh * 33 + kk] = Wp[hh * 256 + kc + kk];
        }
        __syncthreads();
#pragma unroll
        for (int kk = 0; kk < 32; kk++) {
            float w = Wsh[h * 33 + kk];
#pragma unroll
            for (int tt = 0; tt < 8; tt++)
                acc[tt] += w * comb[(g * 8 + tt) * 256 + kc + kk];
        }
    }
    float bb = bp[h];
#pragma unroll
    for (int tt = 0; tt < 8; tt++) {
        float o = fmaxf(acc[tt] + bb, 0.f);
        size_t row = rbase + g * 8 + tt;
        __nv_bfloat16 hi, lo;
        bf16_split(o, hi, lo);
        g_prjA[row * GK + h]       = hi;
        g_prjA[row * GK + 128 + h] = hi;
        g_prjA[row * GK + 256 + h] = lo;
    }
}

// ---------------- K5b: Wfc -> B' = [hi|lo|hi] bf16 ----------------
__global__ void wfc_prep_kernel(const float* __restrict__ Wfc) {
    int j = blockIdx.x * 256 + threadIdx.x;   // over VV*HH/4 float4s
    float4 f = *(const float4*)&Wfc[(size_t)j * 4];
    int row = j >> 5;
    int col = (j & 31) * 4;
    __nv_bfloat16 h[4], l[4];
    bf16_split(f.x, h[0], l[0]);
    bf16_split(f.y, h[1], l[1]);
    bf16_split(f.z, h[2], l[2]);
    bf16_split(f.w, h[3], l[3]);
    size_t base = (size_t)row * GK;
    __nv_bfloat162* p0 = (__nv_bfloat162*)&g_wfcB[base + col];
    __nv_bfloat162* p1 = (__nv_bfloat162*)&g_wfcB[base + 128 + col];
    __nv_bfloat162* p2 = (__nv_bfloat162*)&g_wfcB[base + 256 + col];
    p0[0] = __nv_bfloat162(h[0], h[1]); p0[1] = __nv_bfloat162(h[2], h[3]);
    p1[0] = __nv_bfloat162(l[0], l[1]); p1[1] = __nv_bfloat162(l[2], l[3]);
    p2[0] = __nv_bfloat162(h[0], h[1]); p2[1] = __nv_bfloat162(h[2], h[3]);
}

// ---------------- K6: logits = A'(1024xGK) @ B'(32000xGK)^T + bfc, via mma.sync bf16 ----------------
#define NCHUNK (GK/64)   // 6
__global__ __launch_bounds__(256, 2) void logits_mma_kernel(const float* __restrict__ bfc,
                                                            float* __restrict__ out) {
    extern __shared__ char sm[];
    uint32_t smb = smem_to_u32(sm);
    float* biassh = (float*)(sm + 65536);
    int vbase = blockIdx.x * 128;
    int rbase = blockIdx.y * 128;
    int tid = threadIdx.x;
    int wid = tid >> 5, lane = tid & 31;

    if (tid < 128) biassh[tid] = bfc[vbase + tid];

    auto stage = [&](int s, int c) {
        const char* srcA = (const char*)(g_prjA + (size_t)rbase * GK + c * 64);
        const char* srcB = (const char*)(g_wfcB + (size_t)vbase * GK + c * 64);
#pragma unroll
        for (int it = 0; it < 4; it++) {
            int j = it * 256 + tid;
            int r = j >> 3, cc = j & 7;
            uint32_t swoff = (uint32_t)(r * 128 + ((cc ^ (r & 7)) << 4));
            uint32_t dA = smb + s * 32768 + swoff;
            uint32_t dB = smb + s * 32768 + 16384 + swoff;
            const char* sA = srcA + (size_t)r * (GK * 2) + cc * 16;
            const char* sB = srcB + (size_t)r * (GK * 2) + cc * 16;
            asm volatile("cp.async.cg.shared.global [%0], [%1], 16;" :: "r"(dA), "l"(sA));
            asm volatile("cp.async.cg.shared.global [%0], [%1], 16;" :: "r"(dB), "l"(sB));
        }
        asm volatile("cp.async.commit_group;");
    };

    int warp_m = wid >> 2, warp_n = wid & 3;

    float acc[4][4][4];
#pragma unroll
    for (int i = 0; i < 4; i++)
#pragma unroll
        for (int j = 0; j < 4; j++)
#pragma unroll
            for (int p = 0; p < 4; p++) acc[i][j][p] = 0.f;

    stage(0, 0);
    stage(1, 1);

    int arowc = (lane & 7) + ((lane >> 3) & 1) * 8;
    int chnksel = lane >> 4;

    for (int c = 0; c < NCHUNK; c++) {
        if (c == NCHUNK - 1) { asm volatile("cp.async.wait_group 0;" ::: "memory"); }
        else                 { asm volatile("cp.async.wait_group 1;" ::: "memory"); }
        __syncthreads();
        uint32_t Ab = smb + (c & 1) * 32768;
        uint32_t Bb = Ab + 16384;
#pragma unroll
        for (int kk = 0; kk < 4; kk++) {
            uint32_t a[4][4], bfr[2][4];
            int chnk = kk * 2 + chnksel;
#pragma unroll
            for (int mt = 0; mt < 4; mt++) {
                int row = warp_m * 64 + mt * 16 + arowc;
                uint32_t addr = Ab + row * 128 + ((chnk ^ (row & 7)) << 4);
                asm volatile("ldmatrix.sync.aligned.m8n8.x4.shared.b16 {%0,%1,%2,%3}, [%4];"
                    : "=r"(a[mt][0]), "=r"(a[mt][1]), "=r"(a[mt][2]), "=r"(a[mt][3]) : "r"(addr));
            }
#pragma unroll
            for (int bp = 0; bp < 2; bp++) {
                int row = warp_n * 32 + bp * 16 + arowc;
                uint32_t addr = Bb + row * 128 + ((chnk ^ (row & 7)) << 4);
                asm volatile("ldmatrix.sync.aligned.m8n8.x4.shared.b16 {%0,%1,%2,%3}, [%4];"
                    : "=r"(bfr[bp][0]), "=r"(bfr[bp][1]), "=r"(bfr[bp][2]), "=r"(bfr[bp][3]) : "r"(addr));
            }
#pragma unroll
            for (int mt = 0; mt < 4; mt++)
#pragma unroll
                for (int nt = 0; nt < 4; nt++) {
                    uint32_t b0 = bfr[nt >> 1][(nt & 1) ? 1 : 0];
                    uint32_t b1 = bfr[nt >> 1][(nt & 1) ? 3 : 2];
                    asm volatile("mma.sync.aligned.m16n8k16.row.col.f32.bf16.bf16.f32 "
                        "{%0,%1,%2,%3}, {%4,%5,%6,%7}, {%8,%9}, {%0,%1,%2,%3};"
                        : "+f"(acc[mt][nt][0]), "+f"(acc[mt][nt][1]),
                          "+f"(acc[mt][nt][2]), "+f"(acc[mt][nt][3])
                        : "r"(a[mt][0]), "r"(a[mt][1]), "r"(a[mt][2]), "r"(a[mt][3]),
                          "r"(b0), "r"(b1));
                }
        }
        __syncthreads();
        if (c + 2 < NCHUNK) stage(c & 1, c + 2);
    }

    int rquad = lane >> 2, cpair = (lane & 3) * 2;
#pragma unroll
    for (int mt = 0; mt < 4; mt++) {
#pragma unroll
        for (int nt = 0; nt < 4; nt++) {
            int col = warp_n * 32 + nt * 8 + cpair;
            float bx = biassh[col], by = biassh[col + 1];
            size_t row0 = (size_t)rbase + warp_m * 64 + mt * 16 + rquad;
            float2 v0 = { acc[mt][nt][0] + bx, acc[mt][nt][1] + by };
            float2 v1 = { acc[mt][nt][2] + bx, acc[mt][nt][3] + by };
            *(float2*)&out[row0 * VV + vbase + col]       = v0;
            *(float2*)&out[(row0 + 8) * VV + vbase + col] = v1;
        }
    }
}

// ---------------- launch ----------------
extern "C" void kernel_launch(void* const* d_in, const int* in_sizes, int n_in,
                              void* d_out, int out_size) {
    const int*   x32    = (const int*)  d_in[0];
    const float* hidden = (const float*)d_in[1];
    const float* et     = (const float*)d_in[2];
    const float* W_ih   = (const float*)d_in[3];
    const float* W_hh   = (const float*)d_in[4];
    const float* b_ih   = (const float*)d_in[5];
    const float* b_hh   = (const float*)d_in[6];
    const float* W1     = (const float*)d_in[7];
    const float* W2     = (const float*)d_in[8];
    const float* v      = (const float*)d_in[9];
    const float* Wp     = (const float*)d_in[10];
    const float* bp     = (const float*)d_in[11];
    const float* Wfc    = (const float*)d_in[12];
    const float* bfc    = (const float*)d_in[13];
    float* out = (float*)d_out;

    cudaFuncSetAttribute(qk_kernel,         cudaFuncAttributeMaxDynamicSharedMemorySize, 84480);
    cudaFuncSetAttribute(logits_mma_kernel, cudaFuncAttributeMaxDynamicSharedMemorySize, 66048);

    detect_kernel<<<1, 256>>>(x32);
    embed_kernel<<<RR, HH>>>(x32, et, W_ih, b_ih, b_hh);
    wfc_prep_kernel<<<VV * HH / 1024, 256>>>(Wfc);
    rnn_kernel<<<BB, 128>>>(hidden, W_hh, out + OFF_HID);
    qk_kernel<<<64, 256, 84480>>>(W1, W2);
    attn_kernel<<<RR, 256>>>(v, out + OFF_W);
    proj_kernel<<<64, 256>>>(Wp, bp);
    logits_mma_kernel<<<dim3(VV / 128, RR / 128), 256, 66048>>>(bfc, out);
}

// round 14
// speedup vs baseline: 1.1988x; 1.0344x over previous
#include <cuda_runtime.h>
#include <cuda_bf16.h>
#include <cstdint>

typedef unsigned long long ull;

#define VV 32000
#define EE 32
#define HH 128
#define BB 2
#define TT 512
#define RR (BB*TT)                       // 1024
#define GK 384                           // K of split GEMM: [hi|hi|lo] x [hi|lo|hi]
#define OFF_HID (RR*VV)                  // 32768000
#define OFF_W   (OFF_HID + BB*HH)        // 32768256

// ---------------- scratch (static device globals; no allocation) ----------------
__device__ float g_xp [RR*HH];
__device__ float g_rnn[RR*HH];
__device__ float g_q  [RR*HH];
__device__ float g_k  [RR*HH];
__device__ float g_ctx[RR*HH];
__device__ int   g_x64;
__device__ __align__(16) __nv_bfloat16 g_prjA[RR*GK];
__device__ __align__(16) __nv_bfloat16 g_wfcB[(size_t)VV*GK];

// ---------------- helpers ----------------
__device__ __forceinline__ void fma2(ull &d, ull a, ull b) {
    asm("fma.rn.f32x2 %0, %1, %2, %0;" : "+l"(d) : "l"(a), "l"(b));
}
__device__ __forceinline__ void add2(ull &d, ull a) {
    asm("add.rn.f32x2 %0, %0, %1;" : "+l"(d) : "l"(a));
}
__device__ __forceinline__ float ull_lo(ull u){ return __uint_as_float((unsigned)(u & 0xffffffffull)); }
__device__ __forceinline__ float ull_hi(ull u){ return __uint_as_float((unsigned)(u >> 32)); }

__device__ __forceinline__ float tanh_fast(float x) {
    float e = __expf(2.0f * x);
    return 1.0f - __fdividef(2.0f, e + 1.0f);
}
__device__ __forceinline__ float tanh_approx(float x) {
    float y;
    asm("tanh.approx.f32 %0, %1;" : "=f"(y) : "f"(x));
    return y;
}
__device__ __forceinline__ void bf16_split(float f, __nv_bfloat16 &hi, __nv_bfloat16 &lo) {
    hi = __float2bfloat16(f);
    lo = __float2bfloat16(f - __bfloat162float(hi));
}
__device__ __forceinline__ uint32_t smem_to_u32(const void* p) {
    uint32_t a;
    asm("{ .reg .u64 t; cvta.to.shared.u64 t, %1; cvt.u32.u64 %0, t; }" : "=r"(a) : "l"(p));
    return a;
}

// ---------------- K0: detect int64 vs int32 ids ----------------
__global__ void detect_kernel(const int* __restrict__ x32) {
    __shared__ int bad;
    if (threadIdx.x == 0) bad = 0;
    __syncthreads();
    for (int i = threadIdx.x; i < 512; i += blockDim.x)
        if (x32[2*i + 1] != 0) atomicExch(&bad, 1);
    __syncthreads();
    if (threadIdx.x == 0) g_x64 = bad ? 0 : 1;
}

// ---------------- K1: embedding + input projection ----------------
__global__ void embed_kernel(const int* __restrict__ x32,
                             const float* __restrict__ et,
                             const float* __restrict__ W_ih,
                             const float* __restrict__ b_ih,
                             const float* __restrict__ b_hh) {
    __shared__ float e_sh[EE];
    __shared__ float Wsh[HH * 33];
    int r = blockIdx.x;
    int h = threadIdx.x;
    for (int j = h; j < HH * EE; j += HH) {
        int hh = j >> 5, ee = j & 31;
        Wsh[hh * 33 + ee] = W_ih[j];
    }
    int id = g_x64 ? x32[2 * r] : x32[r];
    if (h < EE) e_sh[h] = et[id * EE + h];
    __syncthreads();
    float acc = b_ih[h] + b_hh[h];
#pragma unroll
    for (int e = 0; e < EE; e++) acc += Wsh[h * 33 + e] * e_sh[e];
    g_xp[r * HH + h] = acc;
}

// ---------------- K2: sequential RNN scan (128 thr, full row per thread, no shuffle) ----------------
__global__ void __launch_bounds__(128, 1) rnn_kernel(const float* __restrict__ hidden,
                                                     const float* __restrict__ W_hh,
                                                     float* __restrict__ out_hid) {
    __shared__ __align__(16) float h_sh[2][HH];
    int b = blockIdx.x;
    int h = threadIdx.x;   // 0..127, one output row per thread

    // thread h holds the FULL W_hh row: 128 weights = 64 packed f32x2 regs
    ull w2[64];
    {
        const ulonglong2* wp = (const ulonglong2*)(W_hh + h * HH);
#pragma unroll
        for (int i = 0; i < 32; i++) { ulonglong2 v = wp[i]; w2[2*i] = v.x; w2[2*i+1] = v.y; }
    }
    h_sh[0][h] = hidden[b * HH + h];
    __syncthreads();

    const float* xpb = g_xp + b * TT * HH;
    float* rnnb = g_rnn + b * TT * HH;

    // xp register pipeline, depth 2
    float x0 = xpb[h];
    float x1 = xpb[HH + h];

#pragma unroll 2
    for (int t = 0; t < TT; t++) {
        int cur = t & 1;
        float xnew = (t + 2 < TT) ? xpb[(t + 2) * HH + h] : 0.f;   // prefetch t+2

        const ulonglong2* hp = (const ulonglong2*)&h_sh[cur][0];
        ull a[8];
#pragma unroll
        for (int c = 0; c < 8; c++) a[c] = 0ull;
        // 64 fma2 spread round-robin over 8 independent chains (8 deep each)
#pragma unroll
        for (int i = 0; i < 32; i++) {
            ulonglong2 u = hp[i];
            fma2(a[(2*i)     & 7], w2[2*i],     u.x);
            fma2(a[(2*i + 1) & 7], w2[2*i + 1], u.y);
        }
        add2(a[0], a[4]);
        add2(a[1], a[5]);
        add2(a[2], a[6]);
        add2(a[3], a[7]);
        add2(a[0], a[2]);
        add2(a[1], a[3]);
        add2(a[0], a[1]);
        float s = ull_lo(a[0]) + ull_hi(a[0]);

        float hn = tanh_fast(x0 + s);
        h_sh[cur ^ 1][h] = hn;
        rnnb[t * HH + h] = hn;

        x0 = x1; x1 = xnew;
        __syncthreads();
    }
    out_hid[b * HH + h] = h_sh[0][h];
}

// ---------------- K3: q = rnn@W1^T, k = rnn@W2^T  (64 rows/block, W loaded once) ----------------
__global__ __launch_bounds__(256, 2) void qk_kernel(const float* __restrict__ W1,
                                                    const float* __restrict__ W2) {
    extern __shared__ float qsm[];
    float* Wt  = qsm;              // [k=128][h=128] pitch 132 (transposed)
    float* rsh = qsm + 128 * 132;  // [r=32][k=128] pitch 132 (reused for 2 groups)
    int wsel = blockIdx.x >> 4, tc = blockIdx.x & 15;   // 16 tiles x 64 rows
    const float* W = wsel ? W2 : W1;
    float* dst = wsel ? g_k : g_q;
    int tid = threadIdx.x;
    int h = tid & 127, rg = tid >> 7;

    // transpose W into smem once per block
#pragma unroll
    for (int it = 0; it < 16; it++) {
        int j = it * 256 + tid;
        int hh = j >> 5, k4 = j & 31;
        float4 f = *(const float4*)&W[hh * HH + k4 * 4];
        Wt[(k4 * 4 + 0) * 132 + hh] = f.x;
        Wt[(k4 * 4 + 1) * 132 + hh] = f.y;
        Wt[(k4 * 4 + 2) * 132 + hh] = f.z;
        Wt[(k4 * 4 + 3) * 132 + hh] = f.w;
    }

    for (int grp = 0; grp < 2; grp++) {
        int rbase = tc * 64 + grp * 32;
        __syncthreads();
#pragma unroll
        for (int it = 0; it < 4; it++) {
            int j = it * 256 + tid;
            int r = j >> 5, k4 = j & 31;
            *(float4*)&rsh[r * 132 + k4 * 4] = *(const float4*)&g_rnn[(rbase + r) * HH + k4 * 4];
        }
        __syncthreads();

        float acc[16];
#pragma unroll
        for (int i = 0; i < 16; i++) acc[i] = 0.f;

        for (int k = 0; k < 128; k += 4) {
            float w0 = Wt[(k + 0) * 132 + h];
            float w1 = Wt[(k + 1) * 132 + h];
            float w2v = Wt[(k + 2) * 132 + h];
            float w3 = Wt[(k + 3) * 132 + h];
#pragma unroll
            for (int rr = 0; rr < 16; rr++) {
                float4 rv = *(const float4*)&rsh[(rg * 16 + rr) * 132 + k];
                acc[rr] += w0 * rv.x + w1 * rv.y + w2v * rv.z + w3 * rv.w;
            }
        }
#pragma unroll
        for (int rr = 0; rr < 16; rr++)
            dst[(rbase + rg * 16 + rr) * HH + h] = acc[rr];
    }
}

// ---------------- K4: additive attention (q/v in regs; largest-t blocks first) ----------------
__global__ void attn_kernel(const float* __restrict__ v, float* __restrict__ wout) {
    __shared__ float q_sh[HH], v_sh[HH];
    __shared__ float ksh[64 * 132];
    __shared__ float sc[TT];
    __shared__ float red[8];
    __shared__ float redval;
    __shared__ float ctxp[HH];

    int bx = blockIdx.x;
    int b = bx >> 9, t = 511 - (bx & 511);   // heavy blocks (large t) launch first
    int tid = threadIdx.x;
    int r = b * TT + t;
    int n = t + 1;

    if (tid < HH) { q_sh[tid] = g_q[r * HH + tid]; v_sh[tid] = v[tid]; }
    __syncthreads();

    int sl = tid >> 2, qq = tid & 3;

    // hoist loop-invariant q/v values into registers (64 regs/thread)
    float qv[32], vv[32];
#pragma unroll
    for (int i = 0; i < 32; i++) {
        qv[i] = q_sh[qq + 4 * i];
        vv[i] = v_sh[qq + 4 * i];
    }

    for (int s0 = 0; s0 < n; s0 += 64) {
        int cnt = min(64, n - s0);
        __syncthreads();
        for (int j = tid; j < cnt * HH; j += 256) {
            int ss = j >> 7, hh = j & 127;
            ksh[ss * 132 + hh] = g_k[(b * TT + s0 + ss) * HH + hh];
        }
        __syncthreads();
        float acc = 0.f;
        if (sl < cnt) {
            const float* kr = &ksh[sl * 132 + qq];
#pragma unroll 8
            for (int i = 0; i < 32; i++)
                acc += vv[i] * tanh_approx(qv[i] + kr[4 * i]);
        }
        acc += __shfl_xor_sync(0xffffffffu, acc, 1);
        acc += __shfl_xor_sync(0xffffffffu, acc, 2);
        if (qq == 0 && sl < cnt) sc[s0 + sl] = acc;
    }
    __syncthreads();

    float m = -1e30f;
    for (int s = tid; s < n; s += 256) m = fmaxf(m, sc[s]);
#pragma unroll
    for (int o = 16; o; o >>= 1) m = fmaxf(m, __shfl_xor_sync(0xffffffffu, m, o));
    if ((tid & 31) == 0) red[tid >> 5] = m;
    __syncthreads();
    if (tid == 0) {
        float mm = red[0];
#pragma unroll
        for (int i = 1; i < 8; i++) mm = fmaxf(mm, red[i]);
        redval = mm;
    }
    __syncthreads();
    m = redval;

    float ssum = 0.f;
    for (int s = tid; s < n; s += 256) {
        float e = __expf(sc[s] - m);
        sc[s] = e;
        ssum += e;
    }
#pragma unroll
    for (int o = 16; o; o >>= 1) ssum += __shfl_xor_sync(0xffffffffu, ssum, o);
    __syncthreads();
    if ((tid & 31) == 0) red[tid >> 5] = ssum;
    __syncthreads();
    if (tid == 0) {
        float s2 = 0.f;
#pragma unroll
        for (int i = 0; i < 8; i++) s2 += red[i];
        redval = s2;
    }
    __syncthreads();
    float inv = __fdividef(1.0f, redval);

    for (int s = tid; s < TT; s += 256) {
        float w = (s < n) ? sc[s] * inv : 0.f;
        if (s < n) sc[s] = w;
        wout[(size_t)r * TT + s] = w;
    }
    __syncthreads();

    int h = tid & 127, g = tid >> 7;
    float acc = 0.f;
    for (int s = g; s < n; s += 2)
        acc += sc[s] * g_rnn[(b * TT + s) * HH + h];
    if (g == 1) ctxp[h] = acc;
    __syncthreads();
    if (g == 0) g_ctx[r * HH + h] = acc + ctxp[h];
}

// ---------------- K5: out = relu([rnn|ctx] @ Wp^T + bp) -> A' = [hi|hi|lo] bf16 ----------------
__global__ void proj_kernel(const float* __restrict__ Wp, const float* __restrict__ bp) {
    __shared__ float comb[16 * 256];
    __shared__ float Wsh[HH * 33];
    int bx = blockIdx.x;
    int b = bx >> 5, tc = bx & 31;
    int tid = threadIdx.x;
    int h = tid & 127, g = tid >> 7;
    int rbase = b * TT + tc * 16;

    for (int j = tid; j < 16 * HH; j += 256) {
        int tt = j >> 7, k = j & 127;
        comb[tt * 256 + k]        = g_rnn[(rbase + tt) * HH + k];
        comb[tt * 256 + 128 + k]  = g_ctx[(rbase + tt) * HH + k];
    }
    float acc[8];
#pragma unroll
    for (int i = 0; i < 8; i++) acc[i] = 0.f;

    for (int kc = 0; kc < 256; kc += 32) {
        __syncthreads();
        for (int j = tid; j < HH * 32; j += 256) {
            int hh = j >> 5, kk = j & 31;
            Wsh[hh * 33 + kk] = Wp[hh * 256 + kc + kk];
        }
        __syncthreads();
#pragma unroll
        for (int kk = 0; kk < 32; kk++) {
            float w = Wsh[h * 33 + kk];
#pragma unroll
            for (int tt = 0; tt < 8; tt++)
                acc[tt] += w * comb[(g * 8 + tt) * 256 + kc + kk];
        }
    }
    float bb = bp[h];
#pragma unroll
    for (int tt = 0; tt < 8; tt++) {
        float o = fmaxf(acc[tt] + bb, 0.f);
        size_t row = rbase + g * 8 + tt;
        __nv_bfloat16 hi, lo;
        bf16_split(o, hi, lo);
        g_prjA[row * GK + h]       = hi;
        g_prjA[row * GK + 128 + h] = hi;
        g_prjA[row * GK + 256 + h] = lo;
    }
}

// ---------------- K5b: Wfc -> B' = [hi|lo|hi] bf16 ----------------
__global__ void wfc_prep_kernel(const float* __restrict__ Wfc) {
    int j = blockIdx.x * 256 + threadIdx.x;   // over VV*HH/4 float4s
    float4 f = *(const float4*)&Wfc[(size_t)j * 4];
    int row = j >> 5;
    int col = (j & 31) * 4;
    __nv_bfloat16 h[4], l[4];
    bf16_split(f.x, h[0], l[0]);
    bf16_split(f.y, h[1], l[1]);
    bf16_split(f.z, h[2], l[2]);
    bf16_split(f.w, h[3], l[3]);
    size_t base = (size_t)row * GK;
    __nv_bfloat162* p0 = (__nv_bfloat162*)&g_wfcB[base + col];
    __nv_bfloat162* p1 = (__nv_bfloat162*)&g_wfcB[base + 128 + col];
    __nv_bfloat162* p2 = (__nv_bfloat162*)&g_wfcB[base + 256 + col];
    p0[0] = __nv_bfloat162(h[0], h[1]); p0[1] = __nv_bfloat162(h[2], h[3]);
    p1[0] = __nv_bfloat162(l[0], l[1]); p1[1] = __nv_bfloat162(l[2], l[3]);
    p2[0] = __nv_bfloat162(h[0], h[1]); p2[1] = __nv_bfloat162(h[2], h[3]);
}

// ---------------- K6: logits = A'(1024xGK) @ B'(32000xGK)^T + bfc, via mma.sync bf16 ----------------
#define NCHUNK (GK/64)   // 6
__global__ __launch_bounds__(256, 2) void logits_mma_kernel(const float* __restrict__ bfc,
                                                            float* __restrict__ out) {
    extern __shared__ char sm[];
    uint32_t smb = smem_to_u32(sm);
    float* biassh = (float*)(sm + 65536);
    int vbase = blockIdx.x * 128;
    int rbase = blockIdx.y * 128;
    int tid = threadIdx.x;
    int wid = tid >> 5, lane = tid & 31;

    if (tid < 128) biassh[tid] = bfc[vbase + tid];

    auto stage = [&](int s, int c) {
        const char* srcA = (const char*)(g_prjA + (size_t)rbase * GK + c * 64);
        const char* srcB = (const char*)(g_wfcB + (size_t)vbase * GK + c * 64);
#pragma unroll
        for (int it = 0; it < 4; it++) {
            int j = it * 256 + tid;
            int r = j >> 3, cc = j & 7;
            uint32_t swoff = (uint32_t)(r * 128 + ((cc ^ (r & 7)) << 4));
            uint32_t dA = smb + s * 32768 + swoff;
            uint32_t dB = smb + s * 32768 + 16384 + swoff;
            const char* sA = srcA + (size_t)r * (GK * 2) + cc * 16;
            const char* sB = srcB + (size_t)r * (GK * 2) + cc * 16;
            asm volatile("cp.async.cg.shared.global [%0], [%1], 16;" :: "r"(dA), "l"(sA));
            asm volatile("cp.async.cg.shared.global [%0], [%1], 16;" :: "r"(dB), "l"(sB));
        }
        asm volatile("cp.async.commit_group;");
    };

    int warp_m = wid >> 2, warp_n = wid & 3;

    float acc[4][4][4];
#pragma unroll
    for (int i = 0; i < 4; i++)
#pragma unroll
        for (int j = 0; j < 4; j++)
#pragma unroll
            for (int p = 0; p < 4; p++) acc[i][j][p] = 0.f;

    stage(0, 0);
    stage(1, 1);

    int arowc = (lane & 7) + ((lane >> 3) & 1) * 8;
    int chnksel = lane >> 4;

    for (int c = 0; c < NCHUNK; c++) {
        if (c == NCHUNK - 1) { asm volatile("cp.async.wait_group 0;" ::: "memory"); }
        else                 { asm volatile("cp.async.wait_group 1;" ::: "memory"); }
        __syncthreads();
        uint32_t Ab = smb + (c & 1) * 32768;
        uint32_t Bb = Ab + 16384;
#pragma unroll
        for (int kk = 0; kk < 4; kk++) {
            uint32_t a[4][4], bfr[2][4];
            int chnk = kk * 2 + chnksel;
#pragma unroll
            for (int mt = 0; mt < 4; mt++) {
                int row = warp_m * 64 + mt * 16 + arowc;
                uint32_t addr = Ab + row * 128 + ((chnk ^ (row & 7)) << 4);
                asm volatile("ldmatrix.sync.aligned.m8n8.x4.shared.b16 {%0,%1,%2,%3}, [%4];"
                    : "=r"(a[mt][0]), "=r"(a[mt][1]), "=r"(a[mt][2]), "=r"(a[mt][3]) : "r"(addr));
            }
#pragma unroll
            for (int bp = 0; bp < 2; bp++) {
                int row = warp_n * 32 + bp * 16 + arowc;
                uint32_t addr = Bb + row * 128 + ((chnk ^ (row & 7)) << 4);
                asm volatile("ldmatrix.sync.aligned.m8n8.x4.shared.b16 {%0,%1,%2,%3}, [%4];"
                    : "=r"(bfr[bp][0]), "=r"(bfr[bp][1]), "=r"(bfr[bp][2]), "=r"(bfr[bp][3]) : "r"(addr));
            }
#pragma unroll
            for (int mt = 0; mt < 4; mt++)
#pragma unroll
                for (int nt = 0; nt < 4; nt++) {
                    uint32_t b0 = bfr[nt >> 1][(nt & 1) ? 1 : 0];
                    uint32_t b1 = bfr[nt >> 1][(nt & 1) ? 3 : 2];
                    asm volatile("mma.sync.aligned.m16n8k16.row.col.f32.bf16.bf16.f32 "
                        "{%0,%1,%2,%3}, {%4,%5,%6,%7}, {%8,%9}, {%0,%1,%2,%3};"
                        : "+f"(acc[mt][nt][0]), "+f"(acc[mt][nt][1]),
                          "+f"(acc[mt][nt][2]), "+f"(acc[mt][nt][3])
                        : "r"(a[mt][0]), "r"(a[mt][1]), "r"(a[mt][2]), "r"(a[mt][3]),
                          "r"(b0), "r"(b1));
                }
        }
        __syncthreads();
        if (c + 2 < NCHUNK) stage(c & 1, c + 2);
    }

    int rquad = lane >> 2, cpair = (lane & 3) * 2;
#pragma unroll
    for (int mt = 0; mt < 4; mt++) {
#pragma unroll
        for (int nt = 0; nt < 4; nt++) {
            int col = warp_n * 32 + nt * 8 + cpair;
            float bx = biassh[col], by = biassh[col + 1];
            size_t row0 = (size_t)rbase + warp_m * 64 + mt * 16 + rquad;
            float2 v0 = { acc[mt][nt][0] + bx, acc[mt][nt][1] + by };
            float2 v1 = { acc[mt][nt][2] + bx, acc[mt][nt][3] + by };
            *(float2*)&out[row0 * VV + vbase + col]       = v0;
            *(float2*)&out[(row0 + 8) * VV + vbase + col] = v1;
        }
    }
}

// ---------------- launch ----------------
extern "C" void kernel_launch(void* const* d_in, const int* in_sizes, int n_in,
                              void* d_out, int out_size) {
    const int*   x32    = (const int*)  d_in[0];
    const float* hidden = (const float*)d_in[1];
    const float* et     = (const float*)d_in[2];
    const float* W_ih   = (const float*)d_in[3];
    const float* W_hh   = (const float*)d_in[4];
    const float* b_ih   = (const float*)d_in[5];
    const float* b_hh   = (const float*)d_in[6];
    const float* W1     = (const float*)d_in[7];
    const float* W2     = (const float*)d_in[8];
    const float* v      = (const float*)d_in[9];
    const float* Wp     = (const float*)d_in[10];
    const float* bp     = (const float*)d_in[11];
    const float* Wfc    = (const float*)d_in[12];
    const float* bfc    = (const float*)d_in[13];
    float* out = (float*)d_out;

    cudaFuncSetAttribute(qk_kernel,         cudaFuncAttributeMaxDynamicSharedMemorySize, 84480);
    cudaFuncSetAttribute(logits_mma_kernel, cudaFuncAttributeMaxDynamicSharedMemorySize, 66048);

    detect_kernel<<<1, 256>>>(x32);
    embed_kernel<<<RR, HH>>>(x32, et, W_ih, b_ih, b_hh);
    wfc_prep_kernel<<<VV * HH / 1024, 256>>>(Wfc);
    rnn_kernel<<<BB, 128>>>(hidden, W_hh, out + OFF_HID);
    qk_kernel<<<32, 256, 84480>>>(W1, W2);
    attn_kernel<<<RR, 256>>>(v, out + OFF_W);
    proj_kernel<<<64, 256>>>(Wp, bp);
    logits_mma_kernel<<<dim3(VV / 128, RR / 128), 256, 66048>>>(bfc, out);
}

// round 16
// speedup vs baseline: 1.2436x; 1.0374x over previous
#include <cuda_runtime.h>
#include <cuda_bf16.h>
#include <cstdint>

typedef unsigned long long ull;

#define VV 32000
#define EE 32
#define HH 128
#define BB 2
#define TT 512
#define RR (BB*TT)                       // 1024
#define GK 384                           // K of split GEMM: [hi|hi|lo] x [hi|lo|hi]
#define OFF_HID (RR*VV)                  // 32768000
#define OFF_W   (OFF_HID + BB*HH)        // 32768256

// ---------------- scratch (static device globals; no allocation) ----------------
__device__ float g_xp [RR*HH];
__device__ float g_rnn[RR*HH];
__device__ float g_q  [RR*HH];
__device__ float g_k  [RR*HH];
__device__ float g_ctx[RR*HH];
__device__ int   g_x64;
__device__ __align__(16) __nv_bfloat16 g_prjA[RR*GK];
__device__ __align__(16) __nv_bfloat16 g_wfcB[(size_t)VV*GK];

// ---------------- helpers ----------------
__device__ __forceinline__ void fma2(ull &d, ull a, ull b) {
    asm("fma.rn.f32x2 %0, %1, %2, %0;" : "+l"(d) : "l"(a), "l"(b));
}
__device__ __forceinline__ void add2(ull &d, ull a) {
    asm("add.rn.f32x2 %0, %0, %1;" : "+l"(d) : "l"(a));
}
__device__ __forceinline__ float ull_lo(ull u){ return __uint_as_float((unsigned)(u & 0xffffffffull)); }
__device__ __forceinline__ float ull_hi(ull u){ return __uint_as_float((unsigned)(u >> 32)); }

__device__ __forceinline__ float tanh_fast(float x) {
    float e = __expf(2.0f * x);
    return 1.0f - __fdividef(2.0f, e + 1.0f);
}
__device__ __forceinline__ float tanh_approx(float x) {
    float y;
    asm("tanh.approx.f32 %0, %1;" : "=f"(y) : "f"(x));
    return y;
}
__device__ __forceinline__ void bf16_split(float f, __nv_bfloat16 &hi, __nv_bfloat16 &lo) {
    hi = __float2bfloat16(f);
    lo = __float2bfloat16(f - __bfloat162float(hi));
}
__device__ __forceinline__ uint32_t smem_to_u32(const void* p) {
    uint32_t a;
    asm("{ .reg .u64 t; cvta.to.shared.u64 t, %1; cvt.u32.u64 %0, t; }" : "=r"(a) : "l"(p));
    return a;
}

// ---------------- K0: detect int64 vs int32 ids ----------------
__global__ void detect_kernel(const int* __restrict__ x32) {
    __shared__ int bad;
    if (threadIdx.x == 0) bad = 0;
    __syncthreads();
    for (int i = threadIdx.x; i < 512; i += blockDim.x)
        if (x32[2*i + 1] != 0) atomicExch(&bad, 1);
    __syncthreads();
    if (threadIdx.x == 0) g_x64 = bad ? 0 : 1;
}

// ---------------- K1: embedding + input projection ----------------
__global__ void embed_kernel(const int* __restrict__ x32,
                             const float* __restrict__ et,
                             const float* __restrict__ W_ih,
                             const float* __restrict__ b_ih,
                             const float* __restrict__ b_hh) {
    __shared__ float e_sh[EE];
    __shared__ float Wsh[HH * 33];
    int r = blockIdx.x;
    int h = threadIdx.x;
    for (int j = h; j < HH * EE; j += HH) {
        int hh = j >> 5, ee = j & 31;
        Wsh[hh * 33 + ee] = W_ih[j];
    }
    int id = g_x64 ? x32[2 * r] : x32[r];
    if (h < EE) e_sh[h] = et[id * EE + h];
    __syncthreads();
    float acc = b_ih[h] + b_hh[h];
#pragma unroll
    for (int e = 0; e < EE; e++) acc += Wsh[h * 33 + e] * e_sh[e];
    g_xp[r * HH + h] = acc;
}

// ---------------- K2: sequential RNN scan (128 thr, full row per thread, no shuffle) ----------------
__global__ void __launch_bounds__(128, 1) rnn_kernel(const float* __restrict__ hidden,
                                                     const float* __restrict__ W_hh,
                                                     float* __restrict__ out_hid) {
    __shared__ __align__(16) float h_sh[2][HH];
    int b = blockIdx.x;
    int h = threadIdx.x;   // 0..127, one output row per thread

    // thread h holds the FULL W_hh row: 128 weights = 64 packed f32x2 regs
    ull w2[64];
    {
        const ulonglong2* wp = (const ulonglong2*)(W_hh + h * HH);
#pragma unroll
        for (int i = 0; i < 32; i++) { ulonglong2 v = wp[i]; w2[2*i] = v.x; w2[2*i+1] = v.y; }
    }
    h_sh[0][h] = hidden[b * HH + h];
    __syncthreads();

    const float* xpb = g_xp + b * TT * HH;
    float* rnnb = g_rnn + b * TT * HH;

    // xp register pipeline, depth 2
    float x0 = xpb[h];
    float x1 = xpb[HH + h];

#pragma unroll 2
    for (int t = 0; t < TT; t++) {
        int cur = t & 1;
        float xnew = (t + 2 < TT) ? xpb[(t + 2) * HH + h] : 0.f;   // prefetch t+2

        const ulonglong2* hp = (const ulonglong2*)&h_sh[cur][0];
        ull a[8];
#pragma unroll
        for (int c = 0; c < 8; c++) a[c] = 0ull;
        // 64 fma2 spread round-robin over 8 independent chains (8 deep each)
#pragma unroll
        for (int i = 0; i < 32; i++) {
            ulonglong2 u = hp[i];
            fma2(a[(2*i)     & 7], w2[2*i],     u.x);
            fma2(a[(2*i + 1) & 7], w2[2*i + 1], u.y);
        }
        add2(a[0], a[4]);
        add2(a[1], a[5]);
        add2(a[2], a[6]);
        add2(a[3], a[7]);
        add2(a[0], a[2]);
        add2(a[1], a[3]);
        add2(a[0], a[1]);
        float s = ull_lo(a[0]) + ull_hi(a[0]);

        float hn = tanh_fast(x0 + s);
        h_sh[cur ^ 1][h] = hn;
        rnnb[t * HH + h] = hn;

        x0 = x1; x1 = xnew;
        __syncthreads();
    }
    out_hid[b * HH + h] = h_sh[0][h];
}

// ---------------- K3: q = rnn@W1^T, k = rnn@W2^T  (64 rows/block, W loaded once) ----------------
__global__ __launch_bounds__(256, 2) void qk_kernel(const float* __restrict__ W1,
                                                    const float* __restrict__ W2) {
    extern __shared__ float qsm[];
    float* Wt  = qsm;              // [k=128][h=128] pitch 132 (transposed)
    float* rsh = qsm + 128 * 132;  // [r=32][k=128] pitch 132 (reused for 2 groups)
    int wsel = blockIdx.x >> 4, tc = blockIdx.x & 15;   // 16 tiles x 64 rows
    const float* W = wsel ? W2 : W1;
    float* dst = wsel ? g_k : g_q;
    int tid = threadIdx.x;
    int h = tid & 127, rg = tid >> 7;

    // transpose W into smem once per block
#pragma unroll
    for (int it = 0; it < 16; it++) {
        int j = it * 256 + tid;
        int hh = j >> 5, k4 = j & 31;
        float4 f = *(const float4*)&W[hh * HH + k4 * 4];
        Wt[(k4 * 4 + 0) * 132 + hh] = f.x;
        Wt[(k4 * 4 + 1) * 132 + hh] = f.y;
        Wt[(k4 * 4 + 2) * 132 + hh] = f.z;
        Wt[(k4 * 4 + 3) * 132 + hh] = f.w;
    }

    for (int grp = 0; grp < 2; grp++) {
        int rbase = tc * 64 + grp * 32;
        __syncthreads();
#pragma unroll
        for (int it = 0; it < 4; it++) {
            int j = it * 256 + tid;
            int r = j >> 5, k4 = j & 31;
            *(float4*)&rsh[r * 132 + k4 * 4] = *(const float4*)&g_rnn[(rbase + r) * HH + k4 * 4];
        }
        __syncthreads();

        float acc[16];
#pragma unroll
        for (int i = 0; i < 16; i++) acc[i] = 0.f;

        for (int k = 0; k < 128; k += 4) {
            float w0 = Wt[(k + 0) * 132 + h];
            float w1 = Wt[(k + 1) * 132 + h];
            float w2v = Wt[(k + 2) * 132 + h];
            float w3 = Wt[(k + 3) * 132 + h];
#pragma unroll
            for (int rr = 0; rr < 16; rr++) {
                float4 rv = *(const float4*)&rsh[(rg * 16 + rr) * 132 + k];
                acc[rr] += w0 * rv.x + w1 * rv.y + w2v * rv.z + w3 * rv.w;
            }
        }
#pragma unroll
        for (int rr = 0; rr < 16; rr++)
            dst[(rbase + rg * 16 + rr) * HH + h] = acc[rr];
    }
}

// ---------------- K4: additive attention — 2 timesteps per block (shared k tiles) ----------------
__global__ __launch_bounds__(256, 2) void attn_kernel(const float* __restrict__ v,
                                                      float* __restrict__ wout) {
    __shared__ float q_sh[2][HH], v_sh[HH];
    __shared__ float ksh[64 * 132];
    __shared__ float sc[2][TT];
    __shared__ float red[8];
    __shared__ float redval;
    __shared__ float ctxp[2][HH];

    int bx = blockIdx.x;
    int b = bx >> 8;                     // 256 pairs per batch
    int pair = 255 - (bx & 255);         // heavy pairs launch first
    int t0 = pair * 2, t1 = t0 + 1;
    int n0 = t0 + 1, n1 = t0 + 2;
    int tid = threadIdx.x;

    if (tid < HH) {
        q_sh[0][tid] = g_q[(b * TT + t0) * HH + tid];
        q_sh[1][tid] = g_q[(b * TT + t1) * HH + tid];
        v_sh[tid] = v[tid];
    }
    __syncthreads();

    int sl = tid >> 2, qq = tid & 3;
    float qv0[32], qv1[32];
#pragma unroll
    for (int i = 0; i < 32; i++) {
        qv0[i] = q_sh[0][qq + 4 * i];
        qv1[i] = q_sh[1][qq + 4 * i];
    }

    for (int s0 = 0; s0 < n1; s0 += 64) {
        int cnt = min(64, n1 - s0);
        __syncthreads();
        for (int j = tid; j < cnt * HH; j += 256) {
            int ss = j >> 7, hh = j & 127;
            ksh[ss * 132 + hh] = g_k[(b * TT + s0 + ss) * HH + hh];
        }
        __syncthreads();
        float acc0 = 0.f, acc1 = 0.f;
        if (sl < cnt) {
            const float* kr = &ksh[sl * 132 + qq];
            const float* vr = &v_sh[qq];
#pragma unroll 8
            for (int i = 0; i < 32; i++) {
                float kk = kr[4 * i];
                float vvv = vr[4 * i];
                acc0 += vvv * tanh_approx(qv0[i] + kk);
                acc1 += vvv * tanh_approx(qv1[i] + kk);
            }
        }
        acc0 += __shfl_xor_sync(0xffffffffu, acc0, 1);
        acc0 += __shfl_xor_sync(0xffffffffu, acc0, 2);
        acc1 += __shfl_xor_sync(0xffffffffu, acc1, 1);
        acc1 += __shfl_xor_sync(0xffffffffu, acc1, 2);
        if (qq == 0 && sl < cnt) {
            int s = s0 + sl;
            if (s < n0) sc[0][s] = acc0;
            sc[1][s] = acc1;
        }
    }
    __syncthreads();

    // two softmaxes (tt = 0, 1); weights (incl. zeros beyond n) stored back to sc
#pragma unroll
    for (int tt = 0; tt < 2; tt++) {
        int n = n0 + tt;
        float* scp = sc[tt];
        float m = -1e30f;
        for (int s = tid; s < n; s += 256) m = fmaxf(m, scp[s]);
#pragma unroll
        for (int o = 16; o; o >>= 1) m = fmaxf(m, __shfl_xor_sync(0xffffffffu, m, o));
        if ((tid & 31) == 0) red[tid >> 5] = m;
        __syncthreads();
        if (tid == 0) {
            float mm = red[0];
#pragma unroll
            for (int i = 1; i < 8; i++) mm = fmaxf(mm, red[i]);
            redval = mm;
        }
        __syncthreads();
        m = redval;

        float ssum = 0.f;
        for (int s = tid; s < n; s += 256) {
            float e = __expf(scp[s] - m);
            scp[s] = e;
            ssum += e;
        }
#pragma unroll
        for (int o = 16; o; o >>= 1) ssum += __shfl_xor_sync(0xffffffffu, ssum, o);
        __syncthreads();
        if ((tid & 31) == 0) red[tid >> 5] = ssum;
        __syncthreads();
        if (tid == 0) {
            float s2 = 0.f;
#pragma unroll
            for (int i = 0; i < 8; i++) s2 += red[i];
            redval = s2;
        }
        __syncthreads();
        float inv = __fdividef(1.0f, redval);

        for (int s = tid; s < TT; s += 256) {
            float w = (s < n) ? scp[s] * inv : 0.f;
            scp[s] = w;    // zeros beyond n so shared ctx loop needs no guard
            wout[(size_t)(b * TT + t0 + tt) * TT + s] = w;
        }
        __syncthreads();
    }

    // shared context pass: both rows read g_rnn once
    int h = tid & 127, g = tid >> 7;
    float a0 = 0.f, a1 = 0.f;
    for (int s = g; s < n1; s += 2) {
        float rv = g_rnn[(b * TT + s) * HH + h];
        a0 += sc[0][s] * rv;
        a1 += sc[1][s] * rv;
    }
    if (g == 1) { ctxp[0][h] = a0; ctxp[1][h] = a1; }
    __syncthreads();
    if (g == 0) {
        g_ctx[(b * TT + t0) * HH + h] = a0 + ctxp[0][h];
        g_ctx[(b * TT + t1) * HH + h] = a1 + ctxp[1][h];
    }
}

// ---------------- K5: out = relu([rnn|ctx] @ Wp^T + bp) -> A' = [hi|hi|lo] bf16 ----------------
__global__ void proj_kernel(const float* __restrict__ Wp, const float* __restrict__ bp) {
    __shared__ float comb[16 * 256];
    __shared__ float Wsh[HH * 33];
    int bx = blockIdx.x;
    int b = bx >> 5, tc = bx & 31;
    int tid = threadIdx.x;
    int h = tid & 127, g = tid >> 7;
    int rbase = b * TT + tc * 16;

    for (int j = tid; j < 16 * HH; j += 256) {
        int tt = j >> 7, k = j & 127;
        comb[tt * 256 + k]        = g_rnn[(rbase + tt) * HH + k];
        comb[tt * 256 + 128 + k]  = g_ctx[(rbase + tt) * HH + k];
    }
    float acc[8];
#pragma unroll
    for (int i = 0; i < 8; i++) acc[i] = 0.f;

    for (int kc = 0; kc < 256; kc += 32) {
        __syncthreads();
        for (int j = tid; j < HH * 32; j += 256) {
            int hh = j >> 5, kk = j & 31;
            Wsh[hh * 33 + kk] = Wp[hh * 256 + kc + kk];
        }
        __syncthreads();
#pragma unroll
        for (int kk = 0; kk < 32; kk++) {
            float w = Wsh[h * 33 + kk];
#pragma unroll
            for (int tt = 0; tt < 8; tt++)
                acc[tt] += w * comb[(g * 8 + tt) * 256 + kc + kk];
        }
    }
    float bb = bp[h];
#pragma unroll
    for (int tt = 0; tt < 8; tt++) {
        float o = fmaxf(acc[tt] + bb, 0.f);
        size_t row = rbase + g * 8 + tt;
        __nv_bfloat16 hi, lo;
        bf16_split(o, hi, lo);
        g_prjA[row * GK + h]       = hi;
        g_prjA[row * GK + 128 + h] = hi;
        g_prjA[row * GK + 256 + h] = lo;
    }
}

// ---------------- K5b: Wfc -> B' = [hi|lo|hi] bf16 ----------------
__global__ void wfc_prep_kernel(const float* __restrict__ Wfc) {
    int j = blockIdx.x * 256 + threadIdx.x;   // over VV*HH/4 float4s
    float4 f = *(const float4*)&Wfc[(size_t)j * 4];
    int row = j >> 5;
    int col = (j & 31) * 4;
    __nv_bfloat16 h[4], l[4];
    bf16_split(f.x, h[0], l[0]);
    bf16_split(f.y, h[1], l[1]);
    bf16_split(f.z, h[2], l[2]);
    bf16_split(f.w, h[3], l[3]);
    size_t base = (size_t)row * GK;
    __nv_bfloat162* p0 = (__nv_bfloat162*)&g_wfcB[base + col];
    __nv_bfloat162* p1 = (__nv_bfloat162*)&g_wfcB[base + 128 + col];
    __nv_bfloat162* p2 = (__nv_bfloat162*)&g_wfcB[base + 256 + col];
    p0[0] = __nv_bfloat162(h[0], h[1]); p0[1] = __nv_bfloat162(h[2], h[3]);
    p1[0] = __nv_bfloat162(l[0], l[1]); p1[1] = __nv_bfloat162(l[2], l[3]);
    p2[0] = __nv_bfloat162(h[0], h[1]); p2[1] = __nv_bfloat162(h[2], h[3]);
}

// ---------------- K6: logits via mma.sync bf16 (row-block = fast grid axis for B' L2 reuse) ----------------
#define NCHUNK (GK/64)   // 6
__global__ __launch_bounds__(256, 2) void logits_mma_kernel(const float* __restrict__ bfc,
                                                            float* __restrict__ out) {
    extern __shared__ char sm[];
    uint32_t smb = smem_to_u32(sm);
    float* biassh = (float*)(sm + 65536);
    int rbase = blockIdx.x * 128;    // fast axis: 8 row-blocks share the same B' tile
    int vbase = blockIdx.y * 128;
    int tid = threadIdx.x;
    int wid = tid >> 5, lane = tid & 31;

    if (tid < 128) biassh[tid] = bfc[vbase + tid];

    auto stage = [&](int s, int c) {
        const char* srcA = (const char*)(g_prjA + (size_t)rbase * GK + c * 64);
        const char* srcB = (const char*)(g_wfcB + (size_t)vbase * GK + c * 64);
#pragma unroll
        for (int it = 0; it < 4; it++) {
            int j = it * 256 + tid;
            int r = j >> 3, cc = j & 7;
            uint32_t swoff = (uint32_t)(r * 128 + ((cc ^ (r & 7)) << 4));
            uint32_t dA = smb + s * 32768 + swoff;
            uint32_t dB = smb + s * 32768 + 16384 + swoff;
            const char* sA = srcA + (size_t)r * (GK * 2) + cc * 16;
            const char* sB = srcB + (size_t)r * (GK * 2) + cc * 16;
            asm volatile("cp.async.cg.shared.global [%0], [%1], 16;" :: "r"(dA), "l"(sA));
            asm volatile("cp.async.cg.shared.global [%0], [%1], 16;" :: "r"(dB), "l"(sB));
        }
        asm volatile("cp.async.commit_group;");
    };

    int warp_m = wid >> 2, warp_n = wid & 3;

    float acc[4][4][4];
#pragma unroll
    for (int i = 0; i < 4; i++)
#pragma unroll
        for (int j = 0; j < 4; j++)
#pragma unroll
            for (int p = 0; p < 4; p++) acc[i][j][p] = 0.f;

    stage(0, 0);
    stage(1, 1);

    int arowc = (lane & 7) + ((lane >> 3) & 1) * 8;
    int chnksel = lane >> 4;

    for (int c = 0; c < NCHUNK; c++) {
        if (c == NCHUNK - 1) { asm volatile("cp.async.wait_group 0;" ::: "memory"); }
        else                 { asm volatile("cp.async.wait_group 1;" ::: "memory"); }
        __syncthreads();
        uint32_t Ab = smb + (c & 1) * 32768;
        uint32_t Bb = Ab + 16384;
#pragma unroll
        for (int kk = 0; kk < 4; kk++) {
            uint32_t a[4][4], bfr[2][4];
            int chnk = kk * 2 + chnksel;
#pragma unroll
            for (int mt = 0; mt < 4; mt++) {
                int row = warp_m * 64 + mt * 16 + arowc;
                uint32_t addr = Ab + row * 128 + ((chnk ^ (row & 7)) << 4);
                asm volatile("ldmatrix.sync.aligned.m8n8.x4.shared.b16 {%0,%1,%2,%3}, [%4];"
                    : "=r"(a[mt][0]), "=r"(a[mt][1]), "=r"(a[mt][2]), "=r"(a[mt][3]) : "r"(addr));
            }
#pragma unroll
            for (int bp = 0; bp < 2; bp++) {
                int row = warp_n * 32 + bp * 16 + arowc;
                uint32_t addr = Bb + row * 128 + ((chnk ^ (row & 7)) << 4);
                asm volatile("ldmatrix.sync.aligned.m8n8.x4.shared.b16 {%0,%1,%2,%3}, [%4];"
                    : "=r"(bfr[bp][0]), "=r"(bfr[bp][1]), "=r"(bfr[bp][2]), "=r"(bfr[bp][3]) : "r"(addr));
            }
#pragma unroll
            for (int mt = 0; mt < 4; mt++)
#pragma unroll
                for (int nt = 0; nt < 4; nt++) {
                    uint32_t b0 = bfr[nt >> 1][(nt & 1) ? 1 : 0];
                    uint32_t b1 = bfr[nt >> 1][(nt & 1) ? 3 : 2];
                    asm volatile("mma.sync.aligned.m16n8k16.row.col.f32.bf16.bf16.f32 "
                        "{%0,%1,%2,%3}, {%4,%5,%6,%7}, {%8,%9}, {%0,%1,%2,%3};"
                        : "+f"(acc[mt][nt][0]), "+f"(acc[mt][nt][1]),
                          "+f"(acc[mt][nt][2]), "+f"(acc[mt][nt][3])
                        : "r"(a[mt][0]), "r"(a[mt][1]), "r"(a[mt][2]), "r"(a[mt][3]),
                          "r"(b0), "r"(b1));
                }
        }
        __syncthreads();
        if (c + 2 < NCHUNK) stage(c & 1, c + 2);
    }

    int rquad = lane >> 2, cpair = (lane & 3) * 2;
#pragma unroll
    for (int mt = 0; mt < 4; mt++) {
#pragma unroll
        for (int nt = 0; nt < 4; nt++) {
            int col = warp_n * 32 + nt * 8 + cpair;
            float bx = biassh[col], by = biassh[col + 1];
            size_t row0 = (size_t)rbase + warp_m * 64 + mt * 16 + rquad;
            float2 v0 = { acc[mt][nt][0] + bx, acc[mt][nt][1] + by };
            float2 v1 = { acc[mt][nt][2] + bx, acc[mt][nt][3] + by };
            *(float2*)&out[row0 * VV + vbase + col]       = v0;
            *(float2*)&out[(row0 + 8) * VV + vbase + col] = v1;
        }
    }
}

// ---------------- launch ----------------
extern "C" void kernel_launch(void* const* d_in, const int* in_sizes, int n_in,
                              void* d_out, int out_size) {
    const int*   x32    = (const int*)  d_in[0];
    const float* hidden = (const float*)d_in[1];
    const float* et     = (const float*)d_in[2];
    const float* W_ih   = (const float*)d_in[3];
    const float* W_hh   = (const float*)d_in[4];
    const float* b_ih   = (const float*)d_in[5];
    const float* b_hh   = (const float*)d_in[6];
    const float* W1     = (const float*)d_in[7];
    const float* W2     = (const float*)d_in[8];
    const float* v      = (const float*)d_in[9];
    const float* Wp     = (const float*)d_in[10];
    const float* bp     = (const float*)d_in[11];
    const float* Wfc    = (const float*)d_in[12];
    const float* bfc    = (const float*)d_in[13];
    float* out = (float*)d_out;

    cudaFuncSetAttribute(qk_kernel,         cudaFuncAttributeMaxDynamicSharedMemorySize, 84480);
    cudaFuncSetAttribute(logits_mma_kernel, cudaFuncAttributeMaxDynamicSharedMemorySize, 66048);

    detect_kernel<<<1, 256>>>(x32);
    embed_kernel<<<RR, HH>>>(x32, et, W_ih, b_ih, b_hh);
    wfc_prep_kernel<<<VV * HH / 1024, 256>>>(Wfc);
    rnn_kernel<<<BB, 128>>>(hidden, W_hh, out + OFF_HID);
    qk_kernel<<<32, 256, 84480>>>(W1, W2);
    attn_kernel<<<RR / 2, 256>>>(v, out + OFF_W);
    proj_kernel<<<64, 256>>>(Wp, bp);
    logits_mma_kernel<<<dim3(RR / 128, VV / 128), 256, 66048>>>(bfc, out);
}